// round 10
// baseline (speedup 1.0000x reference)
#include <cuda_runtime.h>

#define NB 16
#define NP 2048
#define NC 512
#define BP (NB * NP)
#define CHUNK 128
#define JSPLIT 8
#define XTILES 2                       // i-tiles of 1024 per batch
#define GEMM_BLOCKS (BP / 16)          // 2048 blocks, 16 rows each
#define IOU_BLOCKS (NB * XTILES * JSPLIT)  // 256

// ---------------- device scratch (no allocations allowed) ----------------
__device__ float4   g_croi[NB * 3 * NP];   // compacted seed rois, per (b, class)
__device__ float2   g_caux[NB * 3 * NP];   // (area, uint bits of (2047-j))
__device__ int      g_pcnt[NB * 3];        // padded counts (multiple of CHUNK)
__device__ int      g_best[NB * 3 * NP];   // packed (iou&~0x7FF)|(2047-j) as SIGNED key, 0 = none
__device__ int      g_tile[NB * XTILES];   // j-split completion counters
__device__ float    g_S[4];                // per-class loss numerators
__device__ int      g_cnt4[4];             // per-class counts (imbalance)
__device__ unsigned g_done;                // resolver completion counter
__device__ unsigned g_gemm;                // gemm-block completion counter

// ---------------- K1: seeds + scratch init ----------------
__global__ void __launch_bounds__(512) k_seeds(const float4* __restrict__ ps,
                                               const float* __restrict__ labels,
                                               const float4* __restrict__ rois) {
    __shared__ float smax[3][512];
    __shared__ int   sidx[3][512];
    __shared__ int   scnt[3][512];
    __shared__ int   fres[3];
    __shared__ int   fcnt[3];
    __shared__ int   s_pos[3];
    __shared__ unsigned char sbits[NP];

    int b = blockIdx.x;
    int t = threadIdx.x;

    // zero all inter-kernel scratch
    {
        int gid = b * 512 + t;
        for (int idx = gid; idx < NB * 3 * NP; idx += NB * 512) g_best[idx] = 0;
        if (gid < NB * XTILES) g_tile[gid] = 0;
        if (gid >= 64 && gid < 68) { g_S[gid - 64] = 0.0f; g_cnt4[gid - 64] = 0; }
        if (gid == 68) { g_done = 0u; g_gemm = 0u; }
    }
    if (t < 3) s_pos[t] = 0;

    float mx[3] = {-1e30f, -1e30f, -1e30f};
    int   mi[3] = {0, 0, 0};
    int   cn[3] = {0, 0, 0};

#pragma unroll
    for (int m = 0; m < NP / 512; ++m) {
        int j = t + m * 512;                 // ascending within thread -> first-occurrence ties
        float4 s = ps[b * NP + j];
        float sc[3] = {s.x, s.y, s.z};
        unsigned bb = 0;
#pragma unroll
        for (int c = 0; c < 3; ++c) {
            if (sc[c] > 0.5f) { bb |= (1u << c); cn[c]++; }
            if (sc[c] > mx[c]) { mx[c] = sc[c]; mi[c] = j; }
        }
        sbits[j] = (unsigned char)bb;
    }
#pragma unroll
    for (int c = 0; c < 3; ++c) { smax[c][t] = mx[c]; sidx[c][t] = mi[c]; scnt[c][t] = cn[c]; }
    __syncthreads();

    int wp = t >> 5, lane = t & 31;
    if (wp < 3) {
        int c = wp;
        float bm = -1e30f; int bi = 1 << 30; int tc = 0;
        for (int q = lane; q < 512; q += 32) {
            tc += scnt[c][q];
            float v = smax[c][q];
            int   xi = sidx[c][q];
            if (v > bm) { bm = v; bi = xi; }
            else if (v == bm && xi < bi) bi = xi;
        }
#pragma unroll
        for (int off = 16; off; off >>= 1) {
            float ov = __shfl_down_sync(0xffffffffu, bm, off);
            int   oi = __shfl_down_sync(0xffffffffu, bi, off);
            int   oc = __shfl_down_sync(0xffffffffu, tc, off);
            tc += oc;
            if (ov > bm) { bm = ov; bi = oi; }
            else if (ov == bm && oi < bi) bi = oi;
        }
        if (lane == 0) { fres[c] = bi; fcnt[c] = tc; }
    }
    __syncthreads();

    float lab[3] = {labels[b * 4 + 0], labels[b * 4 + 1], labels[b * 4 + 2]};

#pragma unroll
    for (int m = 0; m < NP / 512; ++m) {
        int j = t + m * 512;
        float4 r = rois[b * NP + j];
        float area = (r.z - r.x) * (r.w - r.y);
        unsigned bb = sbits[j];
#pragma unroll
        for (int c = 0; c < 3; ++c) {
            bool sel = false;
            if (lab[c] > 0.0f) {
                if (fcnt[c] <= 1) sel = (j == fres[c]);   // fallback: argmax only
                else              sel = ((bb >> c) & 1u) != 0u;
            }
            if (sel) {
                int pos = atomicAdd(&s_pos[c], 1);
                int idx = (b * 3 + c) * NP + pos;
                g_croi[idx] = r;
                g_caux[idx] = make_float2(area, __uint_as_float((unsigned)(2047 - j)));
            }
        }
    }
    __syncthreads();

    // pad each class list to a CHUNK multiple with harmless zero entries
#pragma unroll
    for (int c = 0; c < 3; ++c) {
        int cnt  = s_pos[c];
        int pcnt = (cnt + (CHUNK - 1)) & ~(CHUNK - 1);
        for (int k = cnt + t; k < pcnt; k += 512) {
            int idx = (b * 3 + c) * NP + k;
            g_croi[idx] = make_float4(0.f, 0.f, 0.f, 0.f);
            g_caux[idx] = make_float2(0.f, __uint_as_float(0u));
        }
        if (t == 0) g_pcnt[b * 3 + c] = pcnt;
    }
}

// ---------------- K2: GEMM (blocks 0..2047) || IoU+resolve+loss (blocks 2048+) ----------------
union SmemK2 {
    struct { float4 sW4[NC]; } g;            // 8 KB
    struct {
        float4 s_roi[CHUNK];
        float2 s_aux[CHUNK];
        float  sS[4];
        int    sC[4];
        int    sFlag;
    } i;
};

__global__ void __launch_bounds__(512) k_fused2(const float4* __restrict__ rois,
                                                const float* __restrict__ pre_score,
                                                const float* __restrict__ x,
                                                const float* __restrict__ Wt,
                                                const float* __restrict__ bias,
                                                float* __restrict__ out, int loss_idx) {
    __shared__ SmemK2 sm;
    int bid = blockIdx.x;
    int tid = threadIdx.x;

    if (bid < GEMM_BLOCKS) {
        // ================= GEMM + softmax =================
        float* sW = (float*)sm.g.sW4;
        for (int k = tid; k < 4 * NC; k += 512) sW[k] = Wt[k];
        __syncthreads();

        int warp = tid >> 5, lane = tid & 31;
        int row  = bid * 16 + warp;
        const float4* xr = (const float4*)(x + (size_t)row * NC);

        float a0 = 0.f, a1 = 0.f, a2 = 0.f, a3 = 0.f;
#pragma unroll
        for (int c4 = 0; c4 < NC / 128; ++c4) {
            int k4 = lane + c4 * 32;
            float4 v  = xr[k4];
            float4 w0 = sm.g.sW4[0 * 128 + k4];
            float4 w1 = sm.g.sW4[1 * 128 + k4];
            float4 w2 = sm.g.sW4[2 * 128 + k4];
            float4 w3 = sm.g.sW4[3 * 128 + k4];
            a0 += v.x * w0.x + v.y * w0.y + v.z * w0.z + v.w * w0.w;
            a1 += v.x * w1.x + v.y * w1.y + v.z * w1.z + v.w * w1.w;
            a2 += v.x * w2.x + v.y * w2.y + v.z * w2.z + v.w * w2.w;
            a3 += v.x * w3.x + v.y * w3.y + v.z * w3.z + v.w * w3.w;
        }
#pragma unroll
        for (int off = 16; off; off >>= 1) {
            a0 += __shfl_down_sync(0xffffffffu, a0, off);
            a1 += __shfl_down_sync(0xffffffffu, a1, off);
            a2 += __shfl_down_sync(0xffffffffu, a2, off);
            a3 += __shfl_down_sync(0xffffffffu, a3, off);
        }
        if (lane == 0) {
            a0 += bias[0]; a1 += bias[1]; a2 += bias[2]; a3 += bias[3];
            float m = fmaxf(fmaxf(a0, a1), fmaxf(a2, a3));
            float e0 = __expf(a0 - m), e1 = __expf(a1 - m), e2 = __expf(a2 - m), e3 = __expf(a3 - m);
            float inv = 1.0f / (e0 + e1 + e2 + e3);
            ((float4*)out)[row] = make_float4(e0 * inv, e1 * inv, e2 * inv, e3 * inv);
        }
        // release: block's logits visible, then count
        __syncthreads();
        if (tid == 0) { __threadfence(); atomicAdd(&g_gemm, 1u); }
        return;
    }

    // ================= IoU part =================
    int ib = bid - GEMM_BLOCKS;           // 0..255
    int b  = ib >> 4;
    int xb = (ib >> 3) & 1;
    int jb = ib & 7;
    int i0 = xb * 1024 + tid;
    int i1 = i0 + 512;

    float4 r0 = rois[b * NP + i0];
    float4 r1 = rois[b * NP + i1];
    float  a0 = (r0.z - r0.x) * (r0.w - r0.y);
    float  a1 = (r1.z - r1.x) * (r1.w - r1.y);

#pragma unroll
    for (int c = 0; c < 3; ++c) {
        int pcnt = g_pcnt[b * 3 + c];
        int bk0 = 0, bk1 = 0;
        for (int base = jb * CHUNK; base < pcnt; base += JSPLIT * CHUNK) {
            __syncthreads();
            if (tid < CHUNK) {
                int g = (b * 3 + c) * NP + base + tid;
                sm.i.s_roi[tid] = g_croi[g];
                sm.i.s_aux[tid] = g_caux[g];
            }
            __syncthreads();
#pragma unroll 4
            for (int e = 0; e < CHUNK; ++e) {
                float4 rj = sm.i.s_roi[e];
                float2 ax = sm.i.s_aux[e];
                // chain i0 (single clamp; negative iou -> sign bit -> loses signed max)
                float ltx0 = fmaxf(r0.x, rj.x), lty0 = fmaxf(r0.y, rj.y);
                float rbx0 = fminf(r0.z, rj.z), rby0 = fminf(r0.w, rj.w);
                float w0 = fmaxf(rbx0 - ltx0, 0.f);
                float h0 = rby0 - lty0;
                float in0 = w0 * h0;
                float iou0 = __fdividef(in0, (a0 + ax.x) - in0);
                int k0 = (int)((__float_as_uint(iou0) & 0xFFFFF800u) | __float_as_uint(ax.y));
                bk0 = max(bk0, k0);
                // chain i1
                float ltx1 = fmaxf(r1.x, rj.x), lty1 = fmaxf(r1.y, rj.y);
                float rbx1 = fminf(r1.z, rj.z), rby1 = fminf(r1.w, rj.w);
                float w1 = fmaxf(rbx1 - ltx1, 0.f);
                float h1 = rby1 - lty1;
                float in1 = w1 * h1;
                float iou1 = __fdividef(in1, (a1 + ax.x) - in1);
                int k1 = (int)((__float_as_uint(iou1) & 0xFFFFF800u) | __float_as_uint(ax.y));
                bk1 = max(bk1, k1);
            }
        }
        if (bk0 > 0) atomicMax(&g_best[(b * 3 + c) * NP + i0], bk0);
        if (bk1 > 0) atomicMax(&g_best[(b * 3 + c) * NP + i1], bk1);
    }

    // elect the last-finishing j-split block of this (b, i-tile) as resolver
    __threadfence();
    if (tid == 0) sm.i.sFlag = (atomicAdd(&g_tile[b * XTILES + xb], 1) == JSPLIT - 1) ? 1 : 0;
    __syncthreads();
    if (!sm.i.sFlag) return;

    if (tid < 4) { sm.i.sS[tid] = 0.0f; sm.i.sC[tid] = 0; }
    // wait for all GEMM blocks (scheduled first; in practice already done)
    if (tid == 0) { while (atomicAdd(&g_gemm, 0u) < GEMM_BLOCKS) __nanosleep(128); }
    __syncthreads();
    __threadfence();   // acquire: peer atomicMax results + gemm logits

#pragma unroll
    for (int q = 0; q < 2; ++q) {
        int i = xb * 1024 + tid + q * 512;
        float I = -1.0f, w = 1.0f;
        int a = 3;
#pragma unroll
        for (int c = 0; c < 3; ++c) {
            int k = __ldcg(&g_best[(b * 3 + c) * NP + i]);
            if (k > 0) {
                float iou = __uint_as_float((unsigned)k & 0xFFFFF800u);
                if (iou >= 0.5f && iou > I) {
                    I = iou;
                    int j = 2047 - (k & 0x7FF);
                    w = pre_score[((b << 11) + j) * 4 + c];
                    a = c;
                }
            }
        }
        float4 lg = __ldcg(&((const float4*)out)[(b << 11) + i]);
        float la = (a == 0) ? lg.x : (a == 1) ? lg.y : (a == 2) ? lg.z : lg.w;
        float p = fminf(fmaxf(la, 1e-7f), 1.0f - 1e-7f);
        float omp = 1.0f - p;
        float term = -__logf(p) * omp * omp * w;   // w_ weight == 1 always (label-gated)
        atomicAdd(&sm.i.sS[a], term);
        atomicAdd(&sm.i.sC[a], 1);
    }
    __syncthreads();
    if (tid < 4) {
        atomicAdd(&g_S[tid], sm.i.sS[tid]);
        atomicAdd(&g_cnt4[tid], sm.i.sC[tid]);
        __threadfence();
    }
    __syncthreads();
    if (tid == 0) sm.i.sFlag = (atomicAdd(&g_done, 1u) == NB * XTILES - 1) ? 1 : 0;
    __syncthreads();
    if (sm.i.sFlag && tid == 0) {
        float l = 0.0f;
#pragma unroll
        for (int c = 0; c < 4; ++c) {
            float s = atomicAdd(&g_S[c], 0.0f);   // coherent L2 read
            int   n = atomicAdd(&g_cnt4[c], 0);
            l += s / ((float)n + 1e-7f);
        }
        out[loss_idx] = l * (1.0f / (float)NB);
    }
}

// ---------------- launch ----------------
extern "C" void kernel_launch(void* const* d_in, const int* in_sizes, int n_in,
                              void* d_out, int out_size) {
    const float* inputs    = (const float*)d_in[0];
    const float* pre_score = (const float*)d_in[1];
    const float* labels    = (const float*)d_in[2];
    const float* rois      = (const float*)d_in[3];
    const float* fcw       = (const float*)d_in[4];
    const float* fcb       = (const float*)d_in[5];
    float* out = (float*)d_out;

    k_seeds<<<NB, 512>>>((const float4*)pre_score, labels, (const float4*)rois);
    k_fused2<<<GEMM_BLOCKS + IOU_BLOCKS, 512>>>((const float4*)rois, pre_score,
                                                inputs, fcw, fcb, out, out_size - 1);
}

// round 12
// speedup vs baseline: 1.6357x; 1.6357x over previous
#include <cuda_runtime.h>

#define NB 16
#define NP 2048
#define NC 512
#define BP (NB * NP)
#define CHUNK 128
#define JSPLIT 8
#define TB 128
#define XTILES (NP / (2 * TB))   // 8 i-tiles of 256

// ---------------- device scratch (no allocations allowed) ----------------
__device__ float4 g_croi[NB * 3 * NP];   // compacted seed rois, per (b, class)
__device__ float2 g_caux[NB * 3 * NP];   // (area, uint bits of (2047-j))
__device__ int    g_pcnt[NB * 3];        // padded counts (multiple of CHUNK)
__device__ int    g_best[NB * 3 * NP];   // packed (iou&~0x7FF)|(2047-j) signed key, 0 = none
__device__ int    g_tile[NB * XTILES];   // j-split completion counters
__device__ float  g_S[4];                // per-class loss numerators
__device__ int    g_cnt4[4];             // per-class counts (imbalance)
__device__ unsigned g_done;              // resolver completion counter

// ---------------- K1: seeds (blocks 0..15) fused with GEMM+softmax (rest) ----------------
union SmemK1 {
    struct {
        float smax[3][512];
        int   sidx[3][512];
        int   scnt[3][512];
        int   fres[3];
        int   fcnt[3];
        int   s_pos[3];
        unsigned char sbits[NP];
    } s;
    struct {
        float4 sW4[NC];        // 4 x 512 floats
    } g;
};

__global__ void __launch_bounds__(512) k_fused1(const float4* __restrict__ ps,
                                                const float* __restrict__ labels,
                                                const float4* __restrict__ rois,
                                                const float* __restrict__ x,
                                                const float* __restrict__ Wt,
                                                const float* __restrict__ bias,
                                                float* __restrict__ out) {
    __shared__ SmemK1 sm;
    int t = threadIdx.x;

    if (blockIdx.x >= NB) {
        // ================= GEMM part =================
        int zid = blockIdx.x - NB;           // 0 .. BP/16-1
        // scratch zeroing spread across early gemm blocks
        if (zid < 192) {
            g_best[zid * 512 + t] = 0;
        } else if (zid == 192) {
            if (t < NB * XTILES) g_tile[t] = 0;
            if (t < 4) { g_S[t] = 0.0f; g_cnt4[t] = 0; }
            if (t == 200) g_done = 0u;
        }

        float* sW = (float*)sm.g.sW4;
        for (int k = t; k < 4 * NC; k += 512) sW[k] = Wt[k];
        __syncthreads();

        int warp = t >> 5, lane = t & 31;
        int row  = zid * 16 + warp;
        const float4* xr = (const float4*)(x + (size_t)row * NC);

        float a0 = 0.f, a1 = 0.f, a2 = 0.f, a3 = 0.f;
#pragma unroll
        for (int c4 = 0; c4 < NC / 128; ++c4) {
            int k4 = lane + c4 * 32;
            float4 v  = xr[k4];
            float4 w0 = sm.g.sW4[0 * 128 + k4];
            float4 w1 = sm.g.sW4[1 * 128 + k4];
            float4 w2 = sm.g.sW4[2 * 128 + k4];
            float4 w3 = sm.g.sW4[3 * 128 + k4];
            a0 += v.x * w0.x + v.y * w0.y + v.z * w0.z + v.w * w0.w;
            a1 += v.x * w1.x + v.y * w1.y + v.z * w1.z + v.w * w1.w;
            a2 += v.x * w2.x + v.y * w2.y + v.z * w2.z + v.w * w2.w;
            a3 += v.x * w3.x + v.y * w3.y + v.z * w3.z + v.w * w3.w;
        }
#pragma unroll
        for (int off = 16; off; off >>= 1) {
            a0 += __shfl_down_sync(0xffffffffu, a0, off);
            a1 += __shfl_down_sync(0xffffffffu, a1, off);
            a2 += __shfl_down_sync(0xffffffffu, a2, off);
            a3 += __shfl_down_sync(0xffffffffu, a3, off);
        }
        if (lane == 0) {
            a0 += bias[0]; a1 += bias[1]; a2 += bias[2]; a3 += bias[3];
            float m = fmaxf(fmaxf(a0, a1), fmaxf(a2, a3));
            float e0 = __expf(a0 - m), e1 = __expf(a1 - m), e2 = __expf(a2 - m), e3 = __expf(a3 - m);
            float inv = 1.0f / (e0 + e1 + e2 + e3);
            ((float4*)out)[row] = make_float4(e0 * inv, e1 * inv, e2 * inv, e3 * inv);
        }
        return;
    }

    // ================= seeds part =================
    int b = blockIdx.x;
    if (t < 3) sm.s.s_pos[t] = 0;

    float mx[3] = {-1e30f, -1e30f, -1e30f};
    int   mi[3] = {0, 0, 0};
    int   cn[3] = {0, 0, 0};

#pragma unroll
    for (int m = 0; m < NP / 512; ++m) {
        int j = t + m * 512;                 // ascending within thread -> first-occurrence ties
        float4 s = ps[b * NP + j];
        float sc[3] = {s.x, s.y, s.z};
        unsigned bb = 0;
#pragma unroll
        for (int c = 0; c < 3; ++c) {
            if (sc[c] > 0.5f) { bb |= (1u << c); cn[c]++; }
            if (sc[c] > mx[c]) { mx[c] = sc[c]; mi[c] = j; }
        }
        sm.s.sbits[j] = (unsigned char)bb;
    }
#pragma unroll
    for (int c = 0; c < 3; ++c) { sm.s.smax[c][t] = mx[c]; sm.s.sidx[c][t] = mi[c]; sm.s.scnt[c][t] = cn[c]; }
    __syncthreads();

    int wp = t >> 5, lane = t & 31;
    if (wp < 3) {
        int c = wp;
        float bm = -1e30f; int bi = 1 << 30; int tc = 0;
        for (int q = lane; q < 512; q += 32) {
            tc += sm.s.scnt[c][q];
            float v = sm.s.smax[c][q];
            int   xi = sm.s.sidx[c][q];
            if (v > bm) { bm = v; bi = xi; }
            else if (v == bm && xi < bi) bi = xi;
        }
#pragma unroll
        for (int off = 16; off; off >>= 1) {
            float ov = __shfl_down_sync(0xffffffffu, bm, off);
            int   oi = __shfl_down_sync(0xffffffffu, bi, off);
            int   oc = __shfl_down_sync(0xffffffffu, tc, off);
            tc += oc;
            if (ov > bm) { bm = ov; bi = oi; }
            else if (ov == bm && oi < bi) bi = oi;
        }
        if (lane == 0) { sm.s.fres[c] = bi; sm.s.fcnt[c] = tc; }
    }
    __syncthreads();

    float lab[3] = {labels[b * 4 + 0], labels[b * 4 + 1], labels[b * 4 + 2]};

#pragma unroll
    for (int m = 0; m < NP / 512; ++m) {
        int j = t + m * 512;
        float4 r = rois[b * NP + j];
        float area = (r.z - r.x) * (r.w - r.y);
        unsigned bb = sm.s.sbits[j];
#pragma unroll
        for (int c = 0; c < 3; ++c) {
            bool sel = false;
            if (lab[c] > 0.0f) {
                if (sm.s.fcnt[c] <= 1) sel = (j == sm.s.fres[c]);   // fallback: argmax only
                else                   sel = ((bb >> c) & 1u) != 0u;
            }
            if (sel) {
                int pos = atomicAdd(&sm.s.s_pos[c], 1);
                int idx = (b * 3 + c) * NP + pos;
                g_croi[idx] = r;
                g_caux[idx] = make_float2(area, __uint_as_float((unsigned)(2047 - j)));
            }
        }
    }
    __syncthreads();

    // pad each class list to a CHUNK multiple with harmless zero entries
#pragma unroll
    for (int c = 0; c < 3; ++c) {
        int cnt  = sm.s.s_pos[c];
        int pcnt = (cnt + (CHUNK - 1)) & ~(CHUNK - 1);
        for (int k = cnt + t; k < pcnt; k += 512) {
            int idx = (b * 3 + c) * NP + k;
            g_croi[idx] = make_float4(0.f, 0.f, 0.f, 0.f);
            g_caux[idx] = make_float2(0.f, __uint_as_float(0u));
        }
        if (t == 0) g_pcnt[b * 3 + c] = pcnt;
    }
}

// ---------------- K2: IoU (2 i/thread, j-split x8) + fused resolve/loss/finalize ----------------
__global__ void __launch_bounds__(TB) k_iou2(const float4* __restrict__ rois,
                                             const float* __restrict__ pre_score,
                                             const float4* __restrict__ logit,
                                             float* __restrict__ out, int loss_idx) {
    __shared__ float4 s_roi[CHUNK];
    __shared__ float2 s_aux[CHUNK];
    __shared__ float  sS[4];
    __shared__ int    sC[4];
    __shared__ int    sFlag;

    int b   = blockIdx.z;
    int xb  = blockIdx.x;
    int jb  = blockIdx.y;
    int tid = threadIdx.x;
    int i0  = xb * (2 * TB) + tid;
    int i1  = i0 + TB;

    if (tid < 4) { sS[tid] = 0.0f; sC[tid] = 0; }

    float4 r0 = rois[b * NP + i0];
    float4 r1 = rois[b * NP + i1];
    float  a0 = (r0.z - r0.x) * (r0.w - r0.y);
    float  a1 = (r1.z - r1.x) * (r1.w - r1.y);

#pragma unroll
    for (int c = 0; c < 3; ++c) {
        int pcnt = g_pcnt[b * 3 + c];
        int bk0 = 0, bk1 = 0;
        for (int base = jb * CHUNK; base < pcnt; base += JSPLIT * CHUNK) {
            __syncthreads();
            int g = (b * 3 + c) * NP + base + tid;   // CHUNK == TB
            s_roi[tid] = g_croi[g];
            s_aux[tid] = g_caux[g];
            __syncthreads();
#pragma unroll 4
            for (int e = 0; e < CHUNK; ++e) {
                float4 rj = s_roi[e];
                float2 ax = s_aux[e];
                // chain i0 (single clamp; non-positive iou loses the signed max)
                float ltx0 = fmaxf(r0.x, rj.x), lty0 = fmaxf(r0.y, rj.y);
                float rbx0 = fminf(r0.z, rj.z), rby0 = fminf(r0.w, rj.w);
                float w0 = fmaxf(rbx0 - ltx0, 0.f);
                float h0 = rby0 - lty0;
                float in0 = w0 * h0;
                float iou0 = __fdividef(in0, (a0 + ax.x) - in0);
                int k0 = (int)((__float_as_uint(iou0) & 0xFFFFF800u) | __float_as_uint(ax.y));
                bk0 = max(bk0, k0);
                // chain i1
                float ltx1 = fmaxf(r1.x, rj.x), lty1 = fmaxf(r1.y, rj.y);
                float rbx1 = fminf(r1.z, rj.z), rby1 = fminf(r1.w, rj.w);
                float w1 = fmaxf(rbx1 - ltx1, 0.f);
                float h1 = rby1 - lty1;
                float in1 = w1 * h1;
                float iou1 = __fdividef(in1, (a1 + ax.x) - in1);
                int k1 = (int)((__float_as_uint(iou1) & 0xFFFFF800u) | __float_as_uint(ax.y));
                bk1 = max(bk1, k1);
            }
        }
        if (bk0 > 0) atomicMax(&g_best[(b * 3 + c) * NP + i0], bk0);
        if (bk1 > 0) atomicMax(&g_best[(b * 3 + c) * NP + i1], bk1);
    }

    // elect the last-finishing j-split block of this (b, i-tile) as resolver
    __threadfence();
    if (tid == 0) sFlag = (atomicAdd(&g_tile[b * XTILES + xb], 1) == JSPLIT - 1) ? 1 : 0;
    __syncthreads();
    if (!sFlag) return;
    __threadfence();   // acquire: peer blocks' atomicMax results visible

#pragma unroll
    for (int q = 0; q < 2; ++q) {
        int i = xb * (2 * TB) + tid + q * TB;
        float I = -1.0f, w = 1.0f;
        int a = 3;
#pragma unroll
        for (int c = 0; c < 3; ++c) {
            int k = __ldcg(&g_best[(b * 3 + c) * NP + i]);
            if (k > 0) {
                float iou = __uint_as_float((unsigned)k & 0xFFFFF800u);
                if (iou >= 0.5f && iou > I) {
                    I = iou;
                    int j = 2047 - (k & 0x7FF);
                    w = pre_score[((b << 11) + j) * 4 + c];
                    a = c;
                }
            }
        }
        float4 lg = logit[(b << 11) + i];
        float la = (a == 0) ? lg.x : (a == 1) ? lg.y : (a == 2) ? lg.z : lg.w;
        float p = fminf(fmaxf(la, 1e-7f), 1.0f - 1e-7f);
        float omp = 1.0f - p;
        float term = -__logf(p) * omp * omp * w;   // w_ weight == 1 always (label-gated)
        atomicAdd(&sS[a], term);
        atomicAdd(&sC[a], 1);
    }
    __syncthreads();
    if (tid < 4) {
        atomicAdd(&g_S[tid], sS[tid]);
        atomicAdd(&g_cnt4[tid], sC[tid]);
        __threadfence();
    }
    __syncthreads();
    if (tid == 0) sFlag = (atomicAdd(&g_done, 1u) == NB * XTILES - 1) ? 1 : 0;
    __syncthreads();
    if (sFlag && tid == 0) {
        float l = 0.0f;
#pragma unroll
        for (int c = 0; c < 4; ++c) {
            float s = atomicAdd(&g_S[c], 0.0f);   // coherent L2 read
            int   n = atomicAdd(&g_cnt4[c], 0);
            l += s / ((float)n + 1e-7f);
        }
        out[loss_idx] = l * (1.0f / (float)NB);
    }
}

// ---------------- launch ----------------
extern "C" void kernel_launch(void* const* d_in, const int* in_sizes, int n_in,
                              void* d_out, int out_size) {
    const float* inputs    = (const float*)d_in[0];
    const float* pre_score = (const float*)d_in[1];
    const float* labels    = (const float*)d_in[2];
    const float* rois      = (const float*)d_in[3];
    const float* fcw       = (const float*)d_in[4];
    const float* fcb       = (const float*)d_in[5];
    float* out = (float*)d_out;

    k_fused1<<<NB + BP / 16, 512>>>((const float4*)pre_score, labels, (const float4*)rois,
                                    inputs, fcw, fcb, out);
    k_iou2<<<dim3(XTILES, JSPLIT, NB), TB>>>((const float4*)rois, pre_score,
                                             (const float4*)out, out, out_size - 1);
}